// round 1
// baseline (speedup 1.0000x reference)
#include <cuda_runtime.h>
#include <math.h>

#define NNODES 20000
#define NEDGES 640000
#define HH 2
#define DD 64
#define HD 128   // H*D
#define LL 4

// ---------------- static device scratch (no allocations allowed) ----------------
__device__ float g_xl[NNODES * HD];      // source transform  [N, H*D]
__device__ float g_xr[NNODES * HD];      // target transform  [N, H*D]
__device__ float g_xa[NNODES * DD];      // ping
__device__ float g_xb[NNODES * DD];      // pong
__device__ int   g_rowptr[NNODES + 1];
__device__ int   g_deg[NNODES];
__device__ int   g_cursor[NNODES];
__device__ int   g_csr_src[NEDGES];

__device__ __forceinline__ const float* sel_ptr(const float* pert, int sel) {
    return sel == 0 ? pert : (sel == 1 ? g_xa : g_xb);
}
__device__ __forceinline__ float* sel_out(int sel) {
    return sel == 1 ? g_xa : g_xb;
}

// ---------------- CSR build ----------------
__global__ void k_zero() {
    int i = blockIdx.x * blockDim.x + threadIdx.x;
    if (i < NNODES) { g_deg[i] = 0; g_cursor[i] = 0; }
}

__global__ void k_hist(const int* __restrict__ dst) {
    int e = blockIdx.x * blockDim.x + threadIdx.x;
    if (e < NEDGES) atomicAdd(&g_deg[dst[e]], 1);
}

__global__ void k_scan() {
    __shared__ int sh[1024];
    __shared__ int carry;
    if (threadIdx.x == 0) carry = 0;
    __syncthreads();
    for (int base = 0; base < NNODES; base += 1024) {
        int i = base + threadIdx.x;
        int v = (i < NNODES) ? g_deg[i] : 0;
        sh[threadIdx.x] = v;
        __syncthreads();
        for (int off = 1; off < 1024; off <<= 1) {
            int t = (threadIdx.x >= off) ? sh[threadIdx.x - off] : 0;
            __syncthreads();
            sh[threadIdx.x] += t;
            __syncthreads();
        }
        int inc = sh[threadIdx.x];
        int c = carry;
        if (i < NNODES) g_rowptr[i + 1] = c + inc;
        __syncthreads();
        if (threadIdx.x == 1023) carry = c + sh[1023];
        __syncthreads();
    }
    if (threadIdx.x == 0) g_rowptr[0] = 0;
}

__global__ void k_scatter(const int* __restrict__ src, const int* __restrict__ dst) {
    int e = blockIdx.x * blockDim.x + threadIdx.x;
    if (e < NEDGES) {
        int d = dst[e];
        int p = g_rowptr[d] + atomicAdd(&g_cursor[d], 1);
        g_csr_src[p] = src[e];
    }
}

// ---------------- fused xl/xr GEMM:  [N,64] @ [64,128] (+bias) twice ----------------
// grid.x = row tiles of 64, grid.y in {0,1,2,3}: y<2 -> Wl->g_xl, y>=2 -> Wr->g_xr
__global__ void k_gemm_lr(const float* __restrict__ pert, int insel,
                          const float* __restrict__ Wl, const float* __restrict__ Wr,
                          const float* __restrict__ bl, const float* __restrict__ br)
{
    __shared__ float As[64][64];
    __shared__ float Bs[64][64];
    const float* x = sel_ptr(pert, insel);
    int tid = threadIdx.x;               // 256 threads
    int m0 = blockIdx.x * 64;
    int c0 = blockIdx.y * 64;            // 0..192 over the 256 logical cols
    const float* W    = (c0 < HD) ? Wl : Wr;
    const float* bvec = (c0 < HD) ? bl : br;
    int wc0 = c0 & (HD - 1);             // column offset within the 128-wide W

    // load x tile [64 x 64]
    for (int i = tid; i < 1024; i += 256) {
        int r = i >> 4, c4 = i & 15;
        int row = m0 + r;
        float4 v = (row < NNODES) ? ((const float4*)x)[row * 16 + c4]
                                  : make_float4(0.f, 0.f, 0.f, 0.f);
        *((float4*)&As[r][c4 * 4]) = v;
    }
    // load W tile [64 x 64]
    for (int i = tid; i < 1024; i += 256) {
        int k = i >> 4, c4 = i & 15;
        float4 v = *(const float4*)&W[k * HD + wc0 + c4 * 4];
        *((float4*)&Bs[k][c4 * 4]) = v;
    }
    __syncthreads();

    int ty = tid >> 4, tx = tid & 15;
    float acc[4][4] = {};
#pragma unroll
    for (int k = 0; k < 64; k++) {
        float a[4], b[4];
#pragma unroll
        for (int j = 0; j < 4; j++) a[j] = As[ty * 4 + j][k];
#pragma unroll
        for (int j = 0; j < 4; j++) b[j] = Bs[k][tx * 4 + j];
#pragma unroll
        for (int i = 0; i < 4; i++)
#pragma unroll
            for (int j = 0; j < 4; j++) acc[i][j] = fmaf(a[i], b[j], acc[i][j]);
    }

    float* out = (c0 < HD) ? g_xl : g_xr;
#pragma unroll
    for (int i = 0; i < 4; i++) {
        int row = m0 + ty * 4 + i;
        if (row < NNODES) {
#pragma unroll
            for (int j = 0; j < 4; j++) {
                int c = wc0 + tx * 4 + j;
                out[row * HD + c] = acc[i][j] + bvec[c];
            }
        }
    }
}

// ---------------- GATv2 attention: one warp per dst node, online softmax ----------------
__global__ void k_attn(const float* __restrict__ att, const float* __restrict__ bias,
                       int outsel)
{
    int w = (blockIdx.x * blockDim.x + threadIdx.x) >> 5;
    int lane = threadIdx.x & 31;
    if (w >= NNODES) return;
    int n = w;

    const float4* xl4 = (const float4*)g_xl;
    const float4* xr4 = (const float4*)g_xr;

    float4 a4 = ((const float4*)att)[lane];   // att[h][d] slice for this lane
    float4 r4 = xr4[n * 32 + lane];           // xr[n] slice

    float m = -1e30f, s = 0.f;
    float4 acc = make_float4(0.f, 0.f, 0.f, 0.f);

    int beg = g_rowptr[n], end = g_rowptr[n + 1];
    float4 vNext = make_float4(0.f, 0.f, 0.f, 0.f);
    if (beg < end) {
        int s0 = g_csr_src[beg];
        vNext = xl4[s0 * 32 + lane];
    }
    for (int p = beg; p < end; ++p) {
        float4 v = vNext;
        if (p + 1 < end) {
            int s2 = g_csr_src[p + 1];
            vNext = xl4[s2 * 32 + lane];      // prefetch next gather
        }
        // e = leaky_relu(xl[src] + xr[dst], 0.2); partial dot with att
        float ex = v.x + r4.x; ex = ex > 0.f ? ex : 0.2f * ex;
        float ey = v.y + r4.y; ey = ey > 0.f ? ey : 0.2f * ey;
        float ez = v.z + r4.z; ez = ez > 0.f ? ez : 0.2f * ez;
        float ew = v.w + r4.w; ew = ew > 0.f ? ew : 0.2f * ew;
        float part = ex * a4.x + ey * a4.y + ez * a4.z + ew * a4.w;
        // reduce within each 16-lane half (one head per half)
#pragma unroll
        for (int off = 1; off < 16; off <<= 1)
            part += __shfl_xor_sync(0xffffffffu, part, off);
        // online softmax update
        float nm = fmaxf(m, part);
        float c  = __expf(m - nm);
        float wg = __expf(part - nm);
        s = s * c + wg;
        acc.x = acc.x * c + wg * v.x;
        acc.y = acc.y * c + wg * v.y;
        acc.z = acc.z * c + wg * v.z;
        acc.w = acc.w * c + wg * v.w;
        m = nm;
    }

    float inv = (s > 0.f) ? (1.f / s) : 0.f;
    float4 o;
    o.x = acc.x * inv; o.y = acc.y * inv; o.z = acc.z * inv; o.w = acc.w * inv;
    // mean over heads: lane l pairs with lane l^16 (same d, other head)
    o.x = 0.5f * (o.x + __shfl_xor_sync(0xffffffffu, o.x, 16));
    o.y = 0.5f * (o.y + __shfl_xor_sync(0xffffffffu, o.y, 16));
    o.z = 0.5f * (o.z + __shfl_xor_sync(0xffffffffu, o.z, 16));
    o.w = 0.5f * (o.w + __shfl_xor_sync(0xffffffffu, o.w, 16));

    if (lane < 16) {
        float4 b4 = ((const float4*)bias)[lane];
        float4 r;
        float t;
        t = o.x + b4.x; r.x = t > 0.f ? t : 0.01f * t;
        t = o.y + b4.y; r.y = t > 0.f ? t : 0.01f * t;
        t = o.z + b4.z; r.z = t > 0.f ? t : 0.01f * t;
        t = o.w + b4.w; r.w = t > 0.f ? t : 0.01f * t;
        ((float4*)sel_out(outsel))[n * 16 + lane] = r;
    }
}

// ---------------- final projection:  [N,64] @ [64,64] + bo, leaky_relu ----------------
__global__ void k_gemm_o(int insel, const float* __restrict__ pert,
                         const float* __restrict__ Wo, const float* __restrict__ bo,
                         float* __restrict__ out)
{
    __shared__ float As[64][64];
    __shared__ float Bs[64][64];
    const float* x = sel_ptr(pert, insel);
    int tid = threadIdx.x;
    int m0 = blockIdx.x * 64;

    for (int i = tid; i < 1024; i += 256) {
        int r = i >> 4, c4 = i & 15;
        int row = m0 + r;
        float4 v = (row < NNODES) ? ((const float4*)x)[row * 16 + c4]
                                  : make_float4(0.f, 0.f, 0.f, 0.f);
        *((float4*)&As[r][c4 * 4]) = v;
    }
    for (int i = tid; i < 1024; i += 256) {
        int k = i >> 4, c4 = i & 15;
        float4 v = *(const float4*)&Wo[k * DD + c4 * 4];
        *((float4*)&Bs[k][c4 * 4]) = v;
    }
    __syncthreads();

    int ty = tid >> 4, tx = tid & 15;
    float acc[4][4] = {};
#pragma unroll
    for (int k = 0; k < 64; k++) {
        float a[4], b[4];
#pragma unroll
        for (int j = 0; j < 4; j++) a[j] = As[ty * 4 + j][k];
#pragma unroll
        for (int j = 0; j < 4; j++) b[j] = Bs[k][tx * 4 + j];
#pragma unroll
        for (int i = 0; i < 4; i++)
#pragma unroll
            for (int j = 0; j < 4; j++) acc[i][j] = fmaf(a[i], b[j], acc[i][j]);
    }

#pragma unroll
    for (int i = 0; i < 4; i++) {
        int row = m0 + ty * 4 + i;
        if (row < NNODES) {
#pragma unroll
            for (int j = 0; j < 4; j++) {
                int c = tx * 4 + j;
                float t = acc[i][j] + bo[c];
                out[row * DD + c] = t > 0.f ? t : 0.01f * t;
            }
        }
    }
}

// ---------------- launch ----------------
extern "C" void kernel_launch(void* const* d_in, const int* in_sizes, int n_in,
                              void* d_out, int out_size)
{
    const int*   ei   = (const int*)d_in[0];     // edge_index [2, E]
    const float* pert = (const float*)d_in[2];   // [N, D]
    const float* Wl   = (const float*)d_in[3];   // [L, D, H*D]
    const float* bl   = (const float*)d_in[4];   // [L, H*D]
    const float* Wr   = (const float*)d_in[5];
    const float* br   = (const float*)d_in[6];
    const float* att  = (const float*)d_in[7];   // [L, H, D]
    const float* bias = (const float*)d_in[8];   // [L, D]
    const float* Wo   = (const float*)d_in[9];   // [D, D]
    const float* bo   = (const float*)d_in[10];  // [D]
    float* out = (float*)d_out;

    const int* src = ei;
    const int* dst = ei + NEDGES;

    // CSR build (per-call, deterministic work)
    k_zero<<<(NNODES + 255) / 256, 256>>>();
    k_hist<<<(NEDGES + 255) / 256, 256>>>(dst);
    k_scan<<<1, 1024>>>();
    k_scatter<<<(NEDGES + 255) / 256, 256>>>(src, dst);

    int insel = 0;  // 0 = pert_emb
    for (int l = 0; l < LL; l++) {
        dim3 g((NNODES + 63) / 64, 4);
        k_gemm_lr<<<g, 256>>>(pert, insel,
                              Wl + (size_t)l * DD * HD, Wr + (size_t)l * DD * HD,
                              bl + (size_t)l * HD,      br + (size_t)l * HD);
        int outsel = (l & 1) ? 2 : 1;
        k_attn<<<(NNODES * 32 + 255) / 256, 256>>>(att + (size_t)l * HD,
                                                   bias + (size_t)l * DD, outsel);
        insel = outsel;
    }
    k_gemm_o<<<(NNODES + 63) / 64, 256>>>(insel, pert, Wo, bo, out);
}

// round 2
// speedup vs baseline: 1.0311x; 1.0311x over previous
#include <cuda_runtime.h>
#include <cuda_fp16.h>
#include <math.h>

#define NNODES 20000
#define NEDGES 640000
#define HH 2
#define DD 64
#define HD 128   // H*D
#define LL 4
#define AST 68   // padded stride for transposed A tile (16B-aligned, conflict-light)

// ---------------- static device scratch ----------------
__device__ __half g_xl[NNODES * HD];     // source transform, fp16 (gathered per edge)
__device__ float  g_xr[NNODES * HD];     // target transform, fp32 (read once per node)
__device__ float  g_xa[NNODES * DD];     // ping
__device__ float  g_xb[NNODES * DD];     // pong
__device__ int    g_rowptr[NNODES + 1];
__device__ int    g_deg[NNODES];
__device__ int    g_cursor[NNODES];
__device__ int    g_csr_src[NEDGES];

__device__ __forceinline__ const float* sel_ptr(const float* pert, int sel) {
    return sel == 0 ? pert : (sel == 1 ? g_xa : g_xb);
}
__device__ __forceinline__ float* sel_out(int sel) {
    return sel == 1 ? g_xa : g_xb;
}

// ---------------- CSR build ----------------
__global__ void k_zero() {
    int i = blockIdx.x * blockDim.x + threadIdx.x;
    if (i < NNODES) { g_deg[i] = 0; g_cursor[i] = 0; }
}

__global__ void k_hist(const int* __restrict__ dst) {
    int e = blockIdx.x * blockDim.x + threadIdx.x;
    if (e < NEDGES) atomicAdd(&g_deg[dst[e]], 1);
}

__global__ void k_scan() {
    __shared__ int sh[1024];
    __shared__ int carry;
    if (threadIdx.x == 0) carry = 0;
    __syncthreads();
    for (int base = 0; base < NNODES; base += 1024) {
        int i = base + threadIdx.x;
        int v = (i < NNODES) ? g_deg[i] : 0;
        sh[threadIdx.x] = v;
        __syncthreads();
        for (int off = 1; off < 1024; off <<= 1) {
            int t = (threadIdx.x >= off) ? sh[threadIdx.x - off] : 0;
            __syncthreads();
            sh[threadIdx.x] += t;
            __syncthreads();
        }
        int inc = sh[threadIdx.x];
        int c = carry;
        if (i < NNODES) g_rowptr[i + 1] = c + inc;
        __syncthreads();
        if (threadIdx.x == 1023) carry = c + sh[1023];
        __syncthreads();
    }
    if (threadIdx.x == 0) g_rowptr[0] = 0;
}

__global__ void k_scatter(const int* __restrict__ src, const int* __restrict__ dst) {
    int e = blockIdx.x * blockDim.x + threadIdx.x;
    if (e < NEDGES) {
        int d = dst[e];
        int p = g_rowptr[d] + atomicAdd(&g_cursor[d], 1);
        g_csr_src[p] = src[e];
    }
}

// ---------------- fused xl/xr GEMM:  [N,64] @ [64,128] (+bias) ----------------
// grid.y in {0,1,2,3}: y<2 -> Wl -> g_xl (fp16), y>=2 -> Wr -> g_xr (fp32)
__global__ void k_gemm_lr(const float* __restrict__ pert, int insel,
                          const float* __restrict__ Wl, const float* __restrict__ Wr,
                          const float* __restrict__ bl, const float* __restrict__ br)
{
    __shared__ float At[64 * AST];   // transposed: At[k*AST + row]
    __shared__ float Bs[64 * 64];
    const float* x = sel_ptr(pert, insel);
    int tid = threadIdx.x;               // 256 threads
    int m0 = blockIdx.x * 64;
    int c0 = blockIdx.y * 64;
    bool isL = (c0 < HD);
    const float* W    = isL ? Wl : Wr;
    const float* bvec = isL ? bl : br;
    int wc0 = c0 & (HD - 1);

    // load x tile transposed
    for (int i = tid; i < 1024; i += 256) {
        int r = i >> 4, c4 = i & 15;
        int row = m0 + r;
        float4 v = (row < NNODES) ? ((const float4*)x)[row * 16 + c4]
                                  : make_float4(0.f, 0.f, 0.f, 0.f);
        At[(c4 * 4 + 0) * AST + r] = v.x;
        At[(c4 * 4 + 1) * AST + r] = v.y;
        At[(c4 * 4 + 2) * AST + r] = v.z;
        At[(c4 * 4 + 3) * AST + r] = v.w;
    }
    // load W tile [64 x 64]
    for (int i = tid; i < 1024; i += 256) {
        int k = i >> 4, c4 = i & 15;
        float4 v = *(const float4*)&W[k * HD + wc0 + c4 * 4];
        *((float4*)&Bs[k * 64 + c4 * 4]) = v;
    }
    __syncthreads();

    int ty = tid >> 4, tx = tid & 15;
    float acc[4][4] = {};
#pragma unroll
    for (int k = 0; k < 64; k++) {
        float4 a4 = *(const float4*)&At[k * AST + ty * 4];
        float4 b4 = *(const float4*)&Bs[k * 64 + tx * 4];
        float a[4] = {a4.x, a4.y, a4.z, a4.w};
        float b[4] = {b4.x, b4.y, b4.z, b4.w};
#pragma unroll
        for (int i = 0; i < 4; i++)
#pragma unroll
            for (int j = 0; j < 4; j++) acc[i][j] = fmaf(a[i], b[j], acc[i][j]);
    }

    if (isL) {
#pragma unroll
        for (int i = 0; i < 4; i++) {
            int row = m0 + ty * 4 + i;
            if (row < NNODES) {
                int c = wc0 + tx * 4;
                __half2 h0 = __floats2half2_rn(acc[i][0] + bvec[c + 0],
                                               acc[i][1] + bvec[c + 1]);
                __half2 h1 = __floats2half2_rn(acc[i][2] + bvec[c + 2],
                                               acc[i][3] + bvec[c + 3]);
                uint2 pk;
                pk.x = *(unsigned*)&h0;
                pk.y = *(unsigned*)&h1;
                *(uint2*)&g_xl[row * HD + c] = pk;
            }
        }
    } else {
#pragma unroll
        for (int i = 0; i < 4; i++) {
            int row = m0 + ty * 4 + i;
            if (row < NNODES) {
#pragma unroll
                for (int j = 0; j < 4; j++) {
                    int c = wc0 + tx * 4 + j;
                    g_xr[row * HD + c] = acc[i][j] + bvec[c];
                }
            }
        }
    }
}

// ---------------- GATv2 attention: one warp per dst node ----------------
// Softmax without max-shift (logits are O(1); shift-invariance makes this exact).
__global__ void k_attn(const float* __restrict__ att, const float* __restrict__ bias,
                       int outsel)
{
    int n = (blockIdx.x * blockDim.x + threadIdx.x) >> 5;
    int lane = threadIdx.x & 31;
    if (n >= NNODES) return;

    const uint2*  xl2 = (const uint2*)g_xl;      // 4 halves per lane
    const float4* xr4 = (const float4*)g_xr;

    float4 a4 = ((const float4*)att)[lane];      // att slice: lanes 0-15 head0, 16-31 head1
    float4 r4 = xr4[n * 32 + lane];              // xr[n] slice

    float s = 0.f;
    float4 acc = make_float4(0.f, 0.f, 0.f, 0.f);

    int beg = g_rowptr[n], end = g_rowptr[n + 1];

    for (int p = beg; p < end; p += 4) {
        uint2 u[4];
#pragma unroll
        for (int i = 0; i < 4; i++) {
            int q = p + i;
            int sI = g_csr_src[q < end ? q : beg];   // safe dup index, keeps MLP=4
            u[i] = xl2[sI * 32 + lane];
        }
#pragma unroll
        for (int i = 0; i < 4; i++) {
            if (p + i < end) {
                float2 lo = __half22float2(*(__half2*)&u[i].x);
                float2 hi = __half22float2(*(__half2*)&u[i].y);
                float ex = lo.x + r4.x; ex = ex > 0.f ? ex : 0.2f * ex;
                float ey = lo.y + r4.y; ey = ey > 0.f ? ey : 0.2f * ey;
                float ez = hi.x + r4.z; ez = ez > 0.f ? ez : 0.2f * ez;
                float ew = hi.y + r4.w; ew = ew > 0.f ? ew : 0.2f * ew;
                float part = ex * a4.x + ey * a4.y + ez * a4.z + ew * a4.w;
#pragma unroll
                for (int off = 1; off < 16; off <<= 1)
                    part += __shfl_xor_sync(0xffffffffu, part, off);
                float w = __expf(part);
                s += w;
                acc.x = fmaf(w, lo.x, acc.x);
                acc.y = fmaf(w, lo.y, acc.y);
                acc.z = fmaf(w, hi.x, acc.z);
                acc.w = fmaf(w, hi.y, acc.w);
            }
        }
    }

    float inv = (end > beg) ? (1.f / s) : 0.f;
    float4 o;
    o.x = acc.x * inv; o.y = acc.y * inv; o.z = acc.z * inv; o.w = acc.w * inv;
    // mean over heads: lane l pairs with lane l^16
    o.x = 0.5f * (o.x + __shfl_xor_sync(0xffffffffu, o.x, 16));
    o.y = 0.5f * (o.y + __shfl_xor_sync(0xffffffffu, o.y, 16));
    o.z = 0.5f * (o.z + __shfl_xor_sync(0xffffffffu, o.z, 16));
    o.w = 0.5f * (o.w + __shfl_xor_sync(0xffffffffu, o.w, 16));

    if (lane < 16) {
        float4 b4 = ((const float4*)bias)[lane];
        float4 r; float t;
        t = o.x + b4.x; r.x = t > 0.f ? t : 0.01f * t;
        t = o.y + b4.y; r.y = t > 0.f ? t : 0.01f * t;
        t = o.z + b4.z; r.z = t > 0.f ? t : 0.01f * t;
        t = o.w + b4.w; r.w = t > 0.f ? t : 0.01f * t;
        ((float4*)sel_out(outsel))[n * 16 + lane] = r;
    }
}

// ---------------- final projection:  [N,64] @ [64,64] + bo, leaky_relu ----------------
__global__ void k_gemm_o(int insel, const float* __restrict__ pert,
                         const float* __restrict__ Wo, const float* __restrict__ bo,
                         float* __restrict__ out)
{
    __shared__ float At[64 * AST];
    __shared__ float Bs[64 * 64];
    const float* x = sel_ptr(pert, insel);
    int tid = threadIdx.x;
    int m0 = blockIdx.x * 64;

    for (int i = tid; i < 1024; i += 256) {
        int r = i >> 4, c4 = i & 15;
        int row = m0 + r;
        float4 v = (row < NNODES) ? ((const float4*)x)[row * 16 + c4]
                                  : make_float4(0.f, 0.f, 0.f, 0.f);
        At[(c4 * 4 + 0) * AST + r] = v.x;
        At[(c4 * 4 + 1) * AST + r] = v.y;
        At[(c4 * 4 + 2) * AST + r] = v.z;
        At[(c4 * 4 + 3) * AST + r] = v.w;
    }
    for (int i = tid; i < 1024; i += 256) {
        int k = i >> 4, c4 = i & 15;
        float4 v = *(const float4*)&Wo[k * DD + c4 * 4];
        *((float4*)&Bs[k * 64 + c4 * 4]) = v;
    }
    __syncthreads();

    int ty = tid >> 4, tx = tid & 15;
    float acc[4][4] = {};
#pragma unroll
    for (int k = 0; k < 64; k++) {
        float4 a4 = *(const float4*)&At[k * AST + ty * 4];
        float4 b4 = *(const float4*)&Bs[k * 64 + tx * 4];
        float a[4] = {a4.x, a4.y, a4.z, a4.w};
        float b[4] = {b4.x, b4.y, b4.z, b4.w};
#pragma unroll
        for (int i = 0; i < 4; i++)
#pragma unroll
            for (int j = 0; j < 4; j++) acc[i][j] = fmaf(a[i], b[j], acc[i][j]);
    }

#pragma unroll
    for (int i = 0; i < 4; i++) {
        int row = m0 + ty * 4 + i;
        if (row < NNODES) {
#pragma unroll
            for (int j = 0; j < 4; j++) {
                int c = tx * 4 + j;
                float t = acc[i][j] + bo[c];
                out[row * DD + c] = t > 0.f ? t : 0.01f * t;
            }
        }
    }
}

// ---------------- launch ----------------
extern "C" void kernel_launch(void* const* d_in, const int* in_sizes, int n_in,
                              void* d_out, int out_size)
{
    const int*   ei   = (const int*)d_in[0];     // edge_index [2, E]
    const float* pert = (const float*)d_in[2];   // [N, D]
    const float* Wl   = (const float*)d_in[3];   // [L, D, H*D]
    const float* bl   = (const float*)d_in[4];   // [L, H*D]
    const float* Wr   = (const float*)d_in[5];
    const float* br   = (const float*)d_in[6];
    const float* att  = (const float*)d_in[7];   // [L, H, D]
    const float* bias = (const float*)d_in[8];   // [L, D]
    const float* Wo   = (const float*)d_in[9];   // [D, D]
    const float* bo   = (const float*)d_in[10];  // [D]
    float* out = (float*)d_out;

    const int* src = ei;
    const int* dst = ei + NEDGES;

    k_zero<<<(NNODES + 255) / 256, 256>>>();
    k_hist<<<(NEDGES + 255) / 256, 256>>>(dst);
    k_scan<<<1, 1024>>>();
    k_scatter<<<(NEDGES + 255) / 256, 256>>>(src, dst);

    int insel = 0;
    for (int l = 0; l < LL; l++) {
        dim3 g((NNODES + 63) / 64, 4);
        k_gemm_lr<<<g, 256>>>(pert, insel,
                              Wl + (size_t)l * DD * HD, Wr + (size_t)l * DD * HD,
                              bl + (size_t)l * HD,      br + (size_t)l * HD);
        int outsel = (l & 1) ? 2 : 1;
        k_attn<<<(NNODES * 32 + 255) / 256, 256>>>(att + (size_t)l * HD,
                                                   bias + (size_t)l * DD, outsel);
        insel = outsel;
    }
    k_gemm_o<<<(NNODES + 63) / 64, 256>>>(insel, pert, Wo, bo, out);
}

// round 4
// speedup vs baseline: 1.3273x; 1.2872x over previous
#include <cuda_runtime.h>
#include <cuda_fp16.h>

#define NNODES 20000
#define NEDGES 640000
#define HD 128
#define DD 64
#define LL 4
#define NPART 20          // ceil(NNODES/1024)
#define AS 72             // As stride in halves (144B rows)
#define BS 68             // Bt stride in halves (136B rows)

// ---------------- static device scratch ----------------
__device__ __half g_xl[NNODES * HD];
__device__ __half g_xr[NNODES * HD];
__device__ __half g_xa[NNODES * DD];
__device__ __half g_xb[NNODES * DD];
__device__ int    g_rowptr[NNODES + 1];
__device__ int    g_deg[NNODES];
__device__ int    g_cursor[NNODES];
__device__ int    g_csr_src[NEDGES];
__device__ int    g_part[32];
__device__ int    g_partoff[32];

__device__ __forceinline__ const __half* hin(int s)  { return s ? g_xb : g_xa; }
__device__ __forceinline__ __half*       hout(int s) { return s ? g_xb : g_xa; }

// ---------------- input conversion: pert fp32 -> g_xa fp16 ----------------
__global__ void k_cvt(const float* __restrict__ pert) {
    int i = blockIdx.x * blockDim.x + threadIdx.x;   // over N*16 float4s
    if (i < NNODES * 16) {
        float4 v = ((const float4*)pert)[i];
        __half2 h0 = __floats2half2_rn(v.x, v.y);
        __half2 h1 = __floats2half2_rn(v.z, v.w);
        uint2 pk;
        pk.x = *(unsigned*)&h0; pk.y = *(unsigned*)&h1;
        ((uint2*)g_xa)[i] = pk;
    }
}

// ---------------- CSR build ----------------
__global__ void k_zero() {
    int i = blockIdx.x * blockDim.x + threadIdx.x;
    if (i < NNODES) { g_deg[i] = 0; g_cursor[i] = 0; }
}

__global__ void k_hist(const int* __restrict__ dst) {
    int e = blockIdx.x * blockDim.x + threadIdx.x;
    if (e < NEDGES) atomicAdd(&g_deg[dst[e]], 1);
}

__global__ void k_scan_part() {
    __shared__ int sh[1024];
    int b = blockIdx.x, t = threadIdx.x;
    int i = b * 1024 + t;
    int v = (i < NNODES) ? g_deg[i] : 0;
    sh[t] = v;
    __syncthreads();
    for (int off = 1; off < 1024; off <<= 1) {
        int u = (t >= off) ? sh[t - off] : 0;
        __syncthreads();
        sh[t] += u;
        __syncthreads();
    }
    if (i < NNODES) g_rowptr[i + 1] = sh[t];
    if (t == 1023) g_part[b] = sh[1023];
}

__global__ void k_scan_top() {
    int t = threadIdx.x;  // 32 threads
    int own = (t < NPART) ? g_part[t] : 0;
    int v = own;
    for (int off = 1; off < 32; off <<= 1) {
        int u = __shfl_up_sync(0xffffffffu, v, off);
        if (t >= off) v += u;
    }
    if (t < NPART) g_partoff[t] = v - own;  // exclusive
}

__global__ void k_scan_add() {
    int b = blockIdx.x, t = threadIdx.x;
    int i = b * 1024 + t;
    if (b > 0 && i < NNODES) g_rowptr[i + 1] += g_partoff[b];
    if (b == 0 && t == 0) g_rowptr[0] = 0;
}

__global__ void k_scatter(const int* __restrict__ src, const int* __restrict__ dst) {
    int e = blockIdx.x * blockDim.x + threadIdx.x;
    if (e < NEDGES) {
        int d = dst[e];
        int p = g_rowptr[d] + atomicAdd(&g_cursor[d], 1);
        g_csr_src[p] = src[e];
    }
}

// ---------------- mma helper ----------------
__device__ __forceinline__ void mma16816(float* c, unsigned a0, unsigned a1,
                                         unsigned a2, unsigned a3,
                                         unsigned b0, unsigned b1) {
    asm volatile(
        "mma.sync.aligned.m16n8k16.row.col.f32.f16.f16.f32 "
        "{%0,%1,%2,%3}, {%4,%5,%6,%7}, {%8,%9}, {%0,%1,%2,%3};\n"
        : "+f"(c[0]), "+f"(c[1]), "+f"(c[2]), "+f"(c[3])
        : "r"(a0), "r"(a1), "r"(a2), "r"(a3), "r"(b0), "r"(b1));
}

// ---------------- xl/xr GEMM (tensor core):  x[N,64] @ W[64,128] (+bias) -> fp16 ----------------
// grid.y 0..3: 64-col slab across logical [Wl | Wr] 256 cols
__global__ __launch_bounds__(128) void k_gemm_lr(
    int insel,
    const float* __restrict__ Wl, const float* __restrict__ Wr,
    const float* __restrict__ bl, const float* __restrict__ br)
{
    __shared__ __half As[64 * AS];
    __shared__ __half Bt[64 * BS];   // Bt[n_local][k]
    const __half* x = hin(insel);
    int tid = threadIdx.x, wid = tid >> 5, lane = tid & 31;
    int m0 = blockIdx.x * 64;
    int c0 = blockIdx.y * 64;
    bool isL = (c0 < HD);
    const float* W  = isL ? Wl : Wr;
    const float* bv = isL ? bl : br;
    int wc0 = c0 & (HD - 1);

    // load x tile (rows of 64 halves = 8 uint4)
    for (int i = tid; i < 512; i += 128) {
        int r = i >> 3, c8 = i & 7;
        int row = m0 + r;
        uint4 v = make_uint4(0u, 0u, 0u, 0u);
        if (row < NNODES) v = ((const uint4*)x)[row * 8 + c8];
        *(uint4*)&As[r * AS + c8 * 8] = v;
    }
    // load + transpose + convert W slab: Bt[n][k]
    for (int i = tid; i < 1024; i += 128) {
        int k = i >> 4, c4 = i & 15;
        float4 v = *(const float4*)&W[k * HD + wc0 + c4 * 4];
        Bt[(c4 * 4 + 0) * BS + k] = __float2half_rn(v.x);
        Bt[(c4 * 4 + 1) * BS + k] = __float2half_rn(v.y);
        Bt[(c4 * 4 + 2) * BS + k] = __float2half_rn(v.z);
        Bt[(c4 * 4 + 3) * BS + k] = __float2half_rn(v.w);
    }
    __syncthreads();

    float acc[8][4];
#pragma unroll
    for (int nt = 0; nt < 8; nt++)
#pragma unroll
        for (int j = 0; j < 4; j++) acc[nt][j] = 0.f;

    int r0 = wid * 16 + (lane >> 2);
    int kc = (lane & 3) * 2;
    int nb = lane >> 2;
#pragma unroll
    for (int ks = 0; ks < 4; ks++) {
        unsigned a0 = *(const unsigned*)&As[r0 * AS + ks * 16 + kc];
        unsigned a1 = *(const unsigned*)&As[(r0 + 8) * AS + ks * 16 + kc];
        unsigned a2 = *(const unsigned*)&As[r0 * AS + ks * 16 + kc + 8];
        unsigned a3 = *(const unsigned*)&As[(r0 + 8) * AS + ks * 16 + kc + 8];
#pragma unroll
        for (int nt = 0; nt < 8; nt++) {
            unsigned b0 = *(const unsigned*)&Bt[(nt * 8 + nb) * BS + ks * 16 + kc];
            unsigned b1 = *(const unsigned*)&Bt[(nt * 8 + nb) * BS + ks * 16 + kc + 8];
            mma16816(acc[nt], a0, a1, a2, a3, b0, b1);
        }
    }

    __half* out = isL ? g_xl : g_xr;
    int colb = (lane & 3) * 2;
    int rowA = m0 + wid * 16 + (lane >> 2);
#pragma unroll
    for (int nt = 0; nt < 8; nt++) {
        int c = wc0 + nt * 8 + colb;
        float bias0 = bv[c], bias1 = bv[c + 1];
        if (rowA < NNODES) {
            __half2 h = __floats2half2_rn(acc[nt][0] + bias0, acc[nt][1] + bias1);
            *(__half2*)&out[rowA * HD + c] = h;
        }
        if (rowA + 8 < NNODES) {
            __half2 h = __floats2half2_rn(acc[nt][2] + bias0, acc[nt][3] + bias1);
            *(__half2*)&out[(rowA + 8) * HD + c] = h;
        }
    }
}

// ---------------- GATv2 attention: 1 warp/node, 2 edge slots of 16 lanes ----------------
// q = lane&15 owns 8 dims (q<8 head0, q>=8 head1); slot = lane>>4 owns alternating edges.
__global__ void k_attn(const float* __restrict__ att, const float* __restrict__ bias,
                       int outsel)
{
    int n = (blockIdx.x * blockDim.x + threadIdx.x) >> 5;
    int lane = threadIdx.x & 31;
    if (n >= NNODES) return;
    int q = lane & 15, slot = lane >> 4;

    // xr[n] slice -> fp32
    uint4 rr = ((const uint4*)g_xr)[n * 16 + q];
    float2 rA = __half22float2(*(__half2*)&rr.x);
    float2 rB = __half22float2(*(__half2*)&rr.y);
    float2 rC = __half22float2(*(__half2*)&rr.z);
    float2 rD = __half22float2(*(__half2*)&rr.w);

    float4 af0 = ((const float4*)att)[q * 2];
    float4 af1 = ((const float4*)att)[q * 2 + 1];

    float s = 0.f;
    float o0 = 0.f, o1 = 0.f, o2 = 0.f, o3 = 0.f, o4 = 0.f, o5 = 0.f, o6 = 0.f, o7 = 0.f;

    int beg = g_rowptr[n], end = g_rowptr[n + 1];
    int deg = end - beg;
    int niter = (deg + 3) >> 2;          // uniform across the warp

    for (int j = 0; j < niter; j++) {
        int p = beg + slot + j * 4;      // this slot's first edge this iter
#pragma unroll
        for (int ii = 0; ii < 2; ii++) {
            int e = p + ii * 2;
            bool valid = e < end;
            int srcI = g_csr_src[valid ? e : beg];
            uint4 u = ((const uint4*)g_xl)[srcI * 16 + q];
            float2 f0 = __half22float2(*(__half2*)&u.x);
            float2 f1 = __half22float2(*(__half2*)&u.y);
            float2 f2 = __half22float2(*(__half2*)&u.z);
            float2 f3 = __half22float2(*(__half2*)&u.w);

            float e0 = f0.x + rA.x, e1 = f0.y + rA.y;
            float e2 = f1.x + rB.x, e3 = f1.y + rB.y;
            float e4 = f2.x + rC.x, e5 = f2.y + rC.y;
            float e6 = f3.x + rD.x, e7 = f3.y + rD.y;
            e0 = fmaxf(e0, 0.2f * e0); e1 = fmaxf(e1, 0.2f * e1);
            e2 = fmaxf(e2, 0.2f * e2); e3 = fmaxf(e3, 0.2f * e3);
            e4 = fmaxf(e4, 0.2f * e4); e5 = fmaxf(e5, 0.2f * e5);
            e6 = fmaxf(e6, 0.2f * e6); e7 = fmaxf(e7, 0.2f * e7);
            float part = e0 * af0.x;
            part = fmaf(e1, af0.y, part);
            part = fmaf(e2, af0.z, part);
            part = fmaf(e3, af0.w, part);
            part = fmaf(e4, af1.x, part);
            part = fmaf(e5, af1.y, part);
            part = fmaf(e6, af1.z, part);
            part = fmaf(e7, af1.w, part);
            // reduce over the 8 lanes of this (edge, head)
            part += __shfl_xor_sync(0xffffffffu, part, 1);
            part += __shfl_xor_sync(0xffffffffu, part, 2);
            part += __shfl_xor_sync(0xffffffffu, part, 4);
            float w = valid ? __expf(part) : 0.f;
            s += w;
            o0 = fmaf(w, f0.x, o0); o1 = fmaf(w, f0.y, o1);
            o2 = fmaf(w, f1.x, o2); o3 = fmaf(w, f1.y, o3);
            o4 = fmaf(w, f2.x, o4); o5 = fmaf(w, f2.y, o5);
            o6 = fmaf(w, f3.x, o6); o7 = fmaf(w, f3.y, o7);
        }
    }

    // combine the two edge slots
    s  += __shfl_xor_sync(0xffffffffu, s, 16);
    o0 += __shfl_xor_sync(0xffffffffu, o0, 16);
    o1 += __shfl_xor_sync(0xffffffffu, o1, 16);
    o2 += __shfl_xor_sync(0xffffffffu, o2, 16);
    o3 += __shfl_xor_sync(0xffffffffu, o3, 16);
    o4 += __shfl_xor_sync(0xffffffffu, o4, 16);
    o5 += __shfl_xor_sync(0xffffffffu, o5, 16);
    o6 += __shfl_xor_sync(0xffffffffu, o6, 16);
    o7 += __shfl_xor_sync(0xffffffffu, o7, 16);

    float inv = (deg > 0) ? (1.f / s) : 0.f;
    o0 *= inv; o1 *= inv; o2 *= inv; o3 *= inv;
    o4 *= inv; o5 *= inv; o6 *= inv; o7 *= inv;

    // head mean: lane q pairs with q^8 (same dim, other head)
    o0 = 0.5f * (o0 + __shfl_xor_sync(0xffffffffu, o0, 8));
    o1 = 0.5f * (o1 + __shfl_xor_sync(0xffffffffu, o1, 8));
    o2 = 0.5f * (o2 + __shfl_xor_sync(0xffffffffu, o2, 8));
    o3 = 0.5f * (o3 + __shfl_xor_sync(0xffffffffu, o3, 8));
    o4 = 0.5f * (o4 + __shfl_xor_sync(0xffffffffu, o4, 8));
    o5 = 0.5f * (o5 + __shfl_xor_sync(0xffffffffu, o5, 8));
    o6 = 0.5f * (o6 + __shfl_xor_sync(0xffffffffu, o6, 8));
    o7 = 0.5f * (o7 + __shfl_xor_sync(0xffffffffu, o7, 8));

    if (lane < 8) {
        float4 b0 = ((const float4*)bias)[q * 2];
        float4 b1 = ((const float4*)bias)[q * 2 + 1];
        float t0 = o0 + b0.x; t0 = t0 > 0.f ? t0 : 0.01f * t0;
        float t1 = o1 + b0.y; t1 = t1 > 0.f ? t1 : 0.01f * t1;
        float t2 = o2 + b0.z; t2 = t2 > 0.f ? t2 : 0.01f * t2;
        float t3 = o3 + b0.w; t3 = t3 > 0.f ? t3 : 0.01f * t3;
        float t4 = o4 + b1.x; t4 = t4 > 0.f ? t4 : 0.01f * t4;
        float t5 = o5 + b1.y; t5 = t5 > 0.f ? t5 : 0.01f * t5;
        float t6 = o6 + b1.z; t6 = t6 > 0.f ? t6 : 0.01f * t6;
        float t7 = o7 + b1.w; t7 = t7 > 0.f ? t7 : 0.01f * t7;
        __half2 h0 = __floats2half2_rn(t0, t1);
        __half2 h1 = __floats2half2_rn(t2, t3);
        __half2 h2 = __floats2half2_rn(t4, t5);
        __half2 h3 = __floats2half2_rn(t6, t7);
        uint4 pk;
        pk.x = *(unsigned*)&h0; pk.y = *(unsigned*)&h1;
        pk.z = *(unsigned*)&h2; pk.w = *(unsigned*)&h3;
        ((uint4*)hout(outsel))[n * 8 + q] = pk;
    }
}

// ---------------- final projection (tensor core): x[N,64] @ Wo[64,64] + bo, leaky -> fp32 ----------------
__global__ __launch_bounds__(128) void k_gemm_o(
    int insel,
    const float* __restrict__ Wo, const float* __restrict__ bo,
    float* __restrict__ out)
{
    __shared__ __half As[64 * AS];
    __shared__ __half Bt[64 * BS];
    const __half* x = hin(insel);
    int tid = threadIdx.x, wid = tid >> 5, lane = tid & 31;
    int m0 = blockIdx.x * 64;

    for (int i = tid; i < 512; i += 128) {
        int r = i >> 3, c8 = i & 7;
        int row = m0 + r;
        uint4 v = make_uint4(0u, 0u, 0u, 0u);
        if (row < NNODES) v = ((const uint4*)x)[row * 8 + c8];
        *(uint4*)&As[r * AS + c8 * 8] = v;
    }
    for (int i = tid; i < 1024; i += 128) {
        int k = i >> 4, c4 = i & 15;
        float4 v = *(const float4*)&Wo[k * DD + c4 * 4];
        Bt[(c4 * 4 + 0) * BS + k] = __float2half_rn(v.x);
        Bt[(c4 * 4 + 1) * BS + k] = __float2half_rn(v.y);
        Bt[(c4 * 4 + 2) * BS + k] = __float2half_rn(v.z);
        Bt[(c4 * 4 + 3) * BS + k] = __float2half_rn(v.w);
    }
    __syncthreads();

    float acc[8][4];
#pragma unroll
    for (int nt = 0; nt < 8; nt++)
#pragma unroll
        for (int j = 0; j < 4; j++) acc[nt][j] = 0.f;

    int r0 = wid * 16 + (lane >> 2);
    int kc = (lane & 3) * 2;
    int nb = lane >> 2;
#pragma unroll
    for (int ks = 0; ks < 4; ks++) {
        unsigned a0 = *(const unsigned*)&As[r0 * AS + ks * 16 + kc];
        unsigned a1 = *(const unsigned*)&As[(r0 + 8) * AS + ks * 16 + kc];
        unsigned a2 = *(const unsigned*)&As[r0 * AS + ks * 16 + kc + 8];
        unsigned a3 = *(const unsigned*)&As[(r0 + 8) * AS + ks * 16 + kc + 8];
#pragma unroll
        for (int nt = 0; nt < 8; nt++) {
            unsigned b0 = *(const unsigned*)&Bt[(nt * 8 + nb) * BS + ks * 16 + kc];
            unsigned b1 = *(const unsigned*)&Bt[(nt * 8 + nb) * BS + ks * 16 + kc + 8];
            mma16816(acc[nt], a0, a1, a2, a3, b0, b1);
        }
    }

    int colb = (lane & 3) * 2;
    int rowA = m0 + wid * 16 + (lane >> 2);
#pragma unroll
    for (int nt = 0; nt < 8; nt++) {
        int c = nt * 8 + colb;
        float bias0 = bo[c], bias1 = bo[c + 1];
        if (rowA < NNODES) {
            float t0 = acc[nt][0] + bias0; t0 = t0 > 0.f ? t0 : 0.01f * t0;
            float t1 = acc[nt][1] + bias1; t1 = t1 > 0.f ? t1 : 0.01f * t1;
            *(float2*)&out[rowA * DD + c] = make_float2(t0, t1);
        }
        if (rowA + 8 < NNODES) {
            float t0 = acc[nt][2] + bias0; t0 = t0 > 0.f ? t0 : 0.01f * t0;
            float t1 = acc[nt][3] + bias1; t1 = t1 > 0.f ? t1 : 0.01f * t1;
            *(float2*)&out[(rowA + 8) * DD + c] = make_float2(t0, t1);
        }
    }
}

// ---------------- launch ----------------
extern "C" void kernel_launch(void* const* d_in, const int* in_sizes, int n_in,
                              void* d_out, int out_size)
{
    const int*   ei   = (const int*)d_in[0];
    const float* pert = (const float*)d_in[2];
    const float* Wl   = (const float*)d_in[3];
    const float* bl   = (const float*)d_in[4];
    const float* Wr   = (const float*)d_in[5];
    const float* br   = (const float*)d_in[6];
    const float* att  = (const float*)d_in[7];
    const float* bias = (const float*)d_in[8];
    const float* Wo   = (const float*)d_in[9];
    const float* bo   = (const float*)d_in[10];
    float* out = (float*)d_out;

    const int* src = ei;
    const int* dst = ei + NEDGES;

    k_cvt<<<(NNODES * 16 + 255) / 256, 256>>>(pert);
    k_zero<<<(NNODES + 255) / 256, 256>>>();
    k_hist<<<(NEDGES + 255) / 256, 256>>>(dst);
    k_scan_part<<<NPART, 1024>>>();
    k_scan_top<<<1, 32>>>();
    k_scan_add<<<NPART, 1024>>>();
    k_scatter<<<(NEDGES + 255) / 256, 256>>>(src, dst);

    for (int l = 0; l < LL; l++) {
        int insel  = (l & 1);        // 0 = g_xa, 1 = g_xb
        int outsel = insel ^ 1;
        dim3 g((NNODES + 63) / 64, 4);
        k_gemm_lr<<<g, 128>>>(insel,
                              Wl + (size_t)l * DD * HD, Wr + (size_t)l * DD * HD,
                              bl + (size_t)l * HD,      br + (size_t)l * HD);
        k_attn<<<(NNODES * 32 + 255) / 256, 256>>>(att + (size_t)l * HD,
                                                   bias + (size_t)l * DD, outsel);
    }
    // after 4 layers the last output landed in g_xa (layer 3: insel=1 -> outsel=0)
    k_gemm_o<<<(NNODES + 63) / 64, 128>>>(0, Wo, bo, out);
}